// round 14
// baseline (speedup 1.0000x reference)
#include <cuda_runtime.h>
#include <cuda_fp16.h>

#define NN    100000
#define EEMAX 4000000
#define INCH  256
#define HID   128
#define OUTC  64
#define NSPLIT 50048   // 391 * 128: node split for prop2/gemm2h pipelining
#define FULLMASK 0xffffffffu

// -------- scratch (device globals; referenced ONLY from device code) --------
__device__ __half g_W16[(size_t)INCH * HID];  // fp16 W1
__device__ __half g_W2[(size_t)HID * 128];    // fp16 [Wmu | Wls] packed
__device__ __half g_H16a[(size_t)NN * HID];   // gemm1 out (prescaled, fp16)
__device__ __half g_H16b[(size_t)NN * HID];   // prop1 out (prescaled, fp16)
__device__ __half g_H16c[(size_t)NN * HID];   // prop2 out (fp16, feeds gemm2)
__device__ float  g_dinv[NN];
__device__ int    g_deg[NN];
__device__ int    g_rowptr[NN + 1];
__device__ int    g_cursor[NN];
__device__ int    g_csr[EEMAX];
__device__ int    g_partial[128];
__device__ unsigned g_scanCtr = 0;
__device__ int    g_idx64;

// ---------------------------------------------------------------------------
// helpers
// ---------------------------------------------------------------------------
__device__ __forceinline__ float4 h4_to_f4(uint2 u) {
    __half2 h0 = *reinterpret_cast<__half2*>(&u.x);
    __half2 h1 = *reinterpret_cast<__half2*>(&u.y);
    float2 f0 = __half22float2(h0);
    float2 f1 = __half22float2(h1);
    return make_float4(f0.x, f0.y, f1.x, f1.y);
}

__device__ __forceinline__ uint2 f4_to_h4(float4 v) {
    __half2 h0 = __floats2half2_rn(v.x, v.y);
    __half2 h1 = __floats2half2_rn(v.z, v.w);
    uint2 u;
    u.x = *reinterpret_cast<unsigned*>(&h0);
    u.y = *reinterpret_cast<unsigned*>(&h1);
    return u;
}

__device__ __forceinline__ void ldsm_x4(unsigned& r0, unsigned& r1,
                                        unsigned& r2, unsigned& r3,
                                        unsigned addr) {
    asm volatile("ldmatrix.sync.aligned.m8n8.x4.shared.b16 {%0,%1,%2,%3}, [%4];"
                 : "=r"(r0), "=r"(r1), "=r"(r2), "=r"(r3) : "r"(addr));
}

__device__ __forceinline__ void ldsm_x4_t(unsigned& r0, unsigned& r1,
                                          unsigned& r2, unsigned& r3,
                                          unsigned addr) {
    asm volatile("ldmatrix.sync.aligned.m8n8.x4.trans.shared.b16 {%0,%1,%2,%3}, [%4];"
                 : "=r"(r0), "=r"(r1), "=r"(r2), "=r"(r3) : "r"(addr));
}

__device__ __forceinline__ void mma16816(float* c, const unsigned* a, const unsigned* b) {
    asm volatile(
        "mma.sync.aligned.m16n8k16.row.col.f32.f16.f16.f32 "
        "{%0,%1,%2,%3}, {%4,%5,%6,%7}, {%8,%9}, {%0,%1,%2,%3};"
        : "+f"(c[0]), "+f"(c[1]), "+f"(c[2]), "+f"(c[3])
        : "r"(a[0]), "r"(a[1]), "r"(a[2]), "r"(a[3]), "r"(b[0]), "r"(b[1]));
}

// ---------------------------------------------------------------------------
// weight conversion kernels
// ---------------------------------------------------------------------------
__global__ void k_cvtW(const float* __restrict__ w) {
    int i = blockIdx.x * blockDim.x + threadIdx.x;
    if (i < INCH * HID / 4)
        ((uint2*)g_W16)[i] = f4_to_h4(((const float4*)w)[i]);
}

__global__ void k_cvtW2(const float* __restrict__ wmu, const float* __restrict__ wls) {
    int i = blockIdx.x * blockDim.x + threadIdx.x;
    if (i < HID * 128) {
        int k = i >> 7, c = i & 127;
        float v = (c < 64) ? wmu[k * OUTC + c] : wls[k * OUTC + (c - 64)];
        g_W2[i] = __float2half_rn(v);
    }
}

// ---------------------------------------------------------------------------
// merged: block 0 = dtype detection; blocks 1.. = zero g_deg
// ---------------------------------------------------------------------------
__global__ void k_detect_zero(const int* __restrict__ ei32) {
    if (blockIdx.x == 0) {
        __shared__ int nz;
        if (threadIdx.x == 0) nz = 0;
        __syncthreads();
        int local = 0;
        for (int i = threadIdx.x; i < 4096; i += blockDim.x)
            if (ei32[2 * i + 1] != 0) local = 1;
        if (local) atomicOr(&nz, 1);
        __syncthreads();
        if (threadIdx.x == 0) g_idx64 = (nz == 0) ? 1 : 0;
    } else {
        int i = (blockIdx.x - 1) * blockDim.x + threadIdx.x;
        if (i < NN) g_deg[i] = 0;
    }
}

__device__ __forceinline__ int load_idx(const void* ei, long long pos) {
    if (g_idx64) return (int)((const long long*)ei)[pos];
    return ((const int*)ei)[pos];
}

// ---------------------------------------------------------------------------
// CSR construction
// ---------------------------------------------------------------------------
__global__ void k_deg(const void* __restrict__ ei, int e) {
    int i = (blockIdx.x * blockDim.x + threadIdx.x) * 4;
    if (i + 4 <= e) {
        int d0 = load_idx(ei, (long long)e + i);
        int d1 = load_idx(ei, (long long)e + i + 1);
        int d2 = load_idx(ei, (long long)e + i + 2);
        int d3 = load_idx(ei, (long long)e + i + 3);
        atomicAdd(&g_deg[d0], 1);
        atomicAdd(&g_deg[d1], 1);
        atomicAdd(&g_deg[d2], 1);
        atomicAdd(&g_deg[d3], 1);
    } else {
        for (int j = i; j < e; j++)
            atomicAdd(&g_deg[load_idx(ei, (long long)e + j)], 1);
    }
}

// scan with last-block top-scan fold (removes the k_scan_top launch)
__global__ __launch_bounds__(1024) void k_scan_block(int n) {
    __shared__ int s[1024];
    __shared__ bool isLast;
    int t = threadIdx.x;
    int i = blockIdx.x * 1024 + t;
    int v = (i < n) ? g_deg[i] : 0;
    s[t] = v;
    __syncthreads();
#pragma unroll
    for (int off = 1; off < 1024; off <<= 1) {
        int x = (t >= off) ? s[t - off] : 0;
        __syncthreads();
        s[t] += x;
        __syncthreads();
    }
    if (i < n) g_rowptr[i] = s[t] - v;
    if (t == 1023) g_partial[blockIdx.x] = s[1023];

    // last block to finish performs the exclusive top-scan of g_partial
    __threadfence();
    if (t == 0) {
        unsigned prev = atomicAdd(&g_scanCtr, 1u);
        isLast = (prev == gridDim.x - 1);
    }
    __syncthreads();
    if (isLast && t == 0) {
        int run = 0;
        for (int b = 0; b < gridDim.x; b++) {
            int x = g_partial[b];
            g_partial[b] = run;
            run += x;
        }
        g_scanCtr = 0;   // reset for next graph replay (determinism)
        __threadfence();
    }
}

__global__ void k_finalize(int n, int e) {
    int i = blockIdx.x * blockDim.x + threadIdx.x;
    if (i < n) {
        int r = g_rowptr[i] + g_partial[i >> 10];
        g_rowptr[i] = r;
        g_cursor[i] = r;
        g_dinv[i]   = rsqrtf((float)g_deg[i] + 1.0f);
        if (i == 0) g_rowptr[n] = e;
    }
}

__global__ void k_scatter(const void* __restrict__ ei, int e) {
    int i = (blockIdx.x * blockDim.x + threadIdx.x) * 4;
    if (i + 4 <= e) {
        int s0 = load_idx(ei, i);
        int s1 = load_idx(ei, i + 1);
        int s2 = load_idx(ei, i + 2);
        int s3 = load_idx(ei, i + 3);
        int d0 = load_idx(ei, (long long)e + i);
        int d1 = load_idx(ei, (long long)e + i + 1);
        int d2 = load_idx(ei, (long long)e + i + 2);
        int d3 = load_idx(ei, (long long)e + i + 3);
        int p0 = atomicAdd(&g_cursor[d0], 1);
        int p1 = atomicAdd(&g_cursor[d1], 1);
        int p2 = atomicAdd(&g_cursor[d2], 1);
        int p3 = atomicAdd(&g_cursor[d3], 1);
        g_csr[p0] = s0;
        g_csr[p1] = s1;
        g_csr[p2] = s2;
        g_csr[p3] = s3;
    } else {
        for (int j = i; j < e; j++) {
            int s = load_idx(ei, j);
            int d = load_idx(ei, (long long)e + j);
            int pos = atomicAdd(&g_cursor[d], 1);
            g_csr[pos] = s;
        }
    }
}

// ---------------------------------------------------------------------------
// GEMM1 (tensor core): g_H16a = fp16( (X @ W1) * dinv[row] )
// ---------------------------------------------------------------------------
#define A_LD 40
#define B_LD 136

__global__ __launch_bounds__(256) void k_gemm1h(const float* __restrict__ X) {
    __shared__ __half As[128 * A_LD];
    __shared__ __half Bs[32 * B_LD];

    int t = threadIdx.x;
    int lane = t & 31;
    int w = t >> 5;
    int wm = w & 3;
    int wn = w >> 2;
    int row0 = blockIdx.x * 128;

    int arow = t >> 1, acol = (t & 1) * 16;
    int brow = t >> 3, bcol = (t & 7) * 16;
    int gr_a = row0 + arow;

    float c[2][8][4];
#pragma unroll
    for (int mi = 0; mi < 2; mi++)
#pragma unroll
        for (int ni = 0; ni < 8; ni++)
#pragma unroll
            for (int q = 0; q < 4; q++) c[mi][ni][q] = 0.f;

    unsigned as_base = (unsigned)__cvta_generic_to_shared(As);
    unsigned bs_base = (unsigned)__cvta_generic_to_shared(Bs);

    for (int k0 = 0; k0 < INCH; k0 += 32) {
        {
            float4 z = make_float4(0, 0, 0, 0);
            float4 f0 = z, f1 = z, f2 = z, f3 = z;
            if (gr_a < NN) {
                const float4* p = (const float4*)(X + (long long)gr_a * INCH + k0 + acol);
                f0 = p[0]; f1 = p[1]; f2 = p[2]; f3 = p[3];
            }
            uint2 h0 = f4_to_h4(f0), h1 = f4_to_h4(f1);
            uint2 h2 = f4_to_h4(f2), h3 = f4_to_h4(f3);
            uint4* d = (uint4*)(As + arow * A_LD + acol);
            d[0] = make_uint4(h0.x, h0.y, h1.x, h1.y);
            d[1] = make_uint4(h2.x, h2.y, h3.x, h3.y);
        }
        {
            const uint4* p = (const uint4*)(g_W16 + (long long)(k0 + brow) * HID + bcol);
            uint4* d = (uint4*)(Bs + brow * B_LD + bcol);
            d[0] = p[0];
            d[1] = p[1];
        }
        __syncthreads();

#pragma unroll
        for (int ks = 0; ks < 32; ks += 16) {
            unsigned a[2][4];
#pragma unroll
            for (int mi = 0; mi < 2; mi++) {
                int m = wm * 32 + mi * 16 + (lane & 15);
                unsigned addr = as_base + (m * A_LD + ks + (lane >> 4) * 8) * 2;
                ldsm_x4(a[mi][0], a[mi][1], a[mi][2], a[mi][3], addr);
            }
            unsigned b[8][2];
#pragma unroll
            for (int nb = 0; nb < 4; nb++) {
                int n0 = wn * 64 + nb * 16;
                unsigned addr = bs_base + ((ks + (lane & 15)) * B_LD + n0 + (lane >> 4) * 8) * 2;
                unsigned r0, r1, r2, r3;
                ldsm_x4_t(r0, r1, r2, r3, addr);
                b[2 * nb][0] = r0;     b[2 * nb][1] = r1;
                b[2 * nb + 1][0] = r2; b[2 * nb + 1][1] = r3;
            }
#pragma unroll
            for (int mi = 0; mi < 2; mi++)
#pragma unroll
                for (int ni = 0; ni < 8; ni++)
                    mma16816(c[mi][ni], a[mi], b[ni]);
        }
        __syncthreads();
    }

#pragma unroll
    for (int mi = 0; mi < 2; mi++) {
        int row_a = row0 + wm * 32 + mi * 16 + (lane >> 2);
        int row_b = row_a + 8;
        float sa = (row_a < NN) ? g_dinv[row_a] : 0.f;
        float sb = (row_b < NN) ? g_dinv[row_b] : 0.f;
#pragma unroll
        for (int ni = 0; ni < 8; ni++) {
            int col = wn * 64 + ni * 8 + (lane & 3) * 2;
            if (row_a < NN) {
                __half2 h = __floats2half2_rn(c[mi][ni][0] * sa, c[mi][ni][1] * sa);
                *(__half2*)(g_H16a + (long long)row_a * HID + col) = h;
            }
            if (row_b < NN) {
                __half2 h = __floats2half2_rn(c[mi][ni][2] * sb, c[mi][ni][3] * sb);
                *(__half2*)(g_H16a + (long long)row_b * HID + col) = h;
            }
        }
    }
}

// ---------------------------------------------------------------------------
// CSR propagation (fp16 gather, fp32 accumulate): warp per node.
// mode=1: fp16 out = h( dinv*relu(dn*sum + b1) )
// mode=2: fp16 out = h( dn*sum )
// ---------------------------------------------------------------------------
__device__ __forceinline__ void prop_body_h(const __half* __restrict__ in,
                                            __half* __restrict__ outh,
                                            const float* __restrict__ bias,
                                            int mode, int nbase, int nend) {
    int node = nbase + (int)((blockIdx.x * (long long)blockDim.x + threadIdx.x) >> 5);
    int lane = threadIdx.x & 31;
    if (node >= nend) return;

    const uint2* IN = (const uint2*)in;
    int beg = g_rowptr[node];
    int end = g_rowptr[node + 1];

    float4 acc = h4_to_f4(IN[(long long)node * 32 + lane]);  // self-loop (pre-scaled)

    int e = beg;
    for (; e + 8 <= end; e += 8) {
        int s0 = g_csr[e];
        int s1 = g_csr[e + 1];
        int s2 = g_csr[e + 2];
        int s3 = g_csr[e + 3];
        int s4 = g_csr[e + 4];
        int s5 = g_csr[e + 5];
        int s6 = g_csr[e + 6];
        int s7 = g_csr[e + 7];
        uint2 u0 = IN[(long long)s0 * 32 + lane];
        uint2 u1 = IN[(long long)s1 * 32 + lane];
        uint2 u2 = IN[(long long)s2 * 32 + lane];
        uint2 u3 = IN[(long long)s3 * 32 + lane];
        uint2 u4 = IN[(long long)s4 * 32 + lane];
        uint2 u5 = IN[(long long)s5 * 32 + lane];
        uint2 u6 = IN[(long long)s6 * 32 + lane];
        uint2 u7 = IN[(long long)s7 * 32 + lane];
        float4 v0 = h4_to_f4(u0), v1 = h4_to_f4(u1), v2 = h4_to_f4(u2), v3 = h4_to_f4(u3);
        float4 v4 = h4_to_f4(u4), v5 = h4_to_f4(u5), v6 = h4_to_f4(u6), v7 = h4_to_f4(u7);
        acc.x += ((v0.x + v1.x) + (v2.x + v3.x)) + ((v4.x + v5.x) + (v6.x + v7.x));
        acc.y += ((v0.y + v1.y) + (v2.y + v3.y)) + ((v4.y + v5.y) + (v6.y + v7.y));
        acc.z += ((v0.z + v1.z) + (v2.z + v3.z)) + ((v4.z + v5.z) + (v6.z + v7.z));
        acc.w += ((v0.w + v1.w) + (v2.w + v3.w)) + ((v4.w + v5.w) + (v6.w + v7.w));
    }
    for (; e + 4 <= end; e += 4) {
        int s0 = g_csr[e];
        int s1 = g_csr[e + 1];
        int s2 = g_csr[e + 2];
        int s3 = g_csr[e + 3];
        float4 v0 = h4_to_f4(IN[(long long)s0 * 32 + lane]);
        float4 v1 = h4_to_f4(IN[(long long)s1 * 32 + lane]);
        float4 v2 = h4_to_f4(IN[(long long)s2 * 32 + lane]);
        float4 v3 = h4_to_f4(IN[(long long)s3 * 32 + lane]);
        acc.x += (v0.x + v1.x) + (v2.x + v3.x);
        acc.y += (v0.y + v1.y) + (v2.y + v3.y);
        acc.z += (v0.z + v1.z) + (v2.z + v3.z);
        acc.w += (v0.w + v1.w) + (v2.w + v3.w);
    }
    for (; e < end; e++) {
        int s = g_csr[e];
        float4 v = h4_to_f4(IN[(long long)s * 32 + lane]);
        acc.x += v.x; acc.y += v.y; acc.z += v.z; acc.w += v.w;
    }

    float dn = g_dinv[node];
    acc.x *= dn; acc.y *= dn; acc.z *= dn; acc.w *= dn;
    if (mode == 1) {
        float4 b = ((const float4*)bias)[lane];
        acc.x = fmaxf(acc.x + b.x, 0.f) * dn;
        acc.y = fmaxf(acc.y + b.y, 0.f) * dn;
        acc.z = fmaxf(acc.z + b.z, 0.f) * dn;
        acc.w = fmaxf(acc.w + b.w, 0.f) * dn;
    }
    ((uint2*)outh)[(long long)node * 32 + lane] = f4_to_h4(acc);
}

__global__ __launch_bounds__(256) void k_prop1(const float* __restrict__ b1) {
    prop_body_h(g_H16a, g_H16b, b1, 1, 0, NN);
}

__global__ __launch_bounds__(256) void k_prop2(int nbase, int nend) {
    prop_body_h(g_H16b, g_H16c, (const float*)0, 2, nbase, nend);
}

// ---------------------------------------------------------------------------
// GEMM2 (tensor core): [mu | ls] = g_H16c @ g_W2 + bias  (fp32 out)
// rowOff: node-range offset for pipelined halves.
// ---------------------------------------------------------------------------
__global__ __launch_bounds__(256) void k_gemm2h(const float* __restrict__ bmu,
                                                const float* __restrict__ bls,
                                                float* __restrict__ out,
                                                int rowOff) {
    __shared__ __half As[128 * A_LD];
    __shared__ __half Bs[32 * B_LD];

    int t = threadIdx.x;
    int lane = t & 31;
    int w = t >> 5;
    int wm = w & 3;
    int wn = w >> 2;
    int row0 = rowOff + blockIdx.x * 128;

    int arow = t >> 1, acol = (t & 1) * 16;
    int brow = t >> 3, bcol = (t & 7) * 16;
    int gr_a = row0 + arow;

    float c[2][8][4];
#pragma unroll
    for (int mi = 0; mi < 2; mi++)
#pragma unroll
        for (int ni = 0; ni < 8; ni++)
#pragma unroll
            for (int q = 0; q < 4; q++) c[mi][ni][q] = 0.f;

    unsigned as_base = (unsigned)__cvta_generic_to_shared(As);
    unsigned bs_base = (unsigned)__cvta_generic_to_shared(Bs);

    for (int k0 = 0; k0 < HID; k0 += 32) {
        {
            uint4 z = make_uint4(0, 0, 0, 0);
            uint4 v0 = z, v1 = z;
            if (gr_a < NN) {
                const uint4* p = (const uint4*)(g_H16c + (long long)gr_a * HID + k0 + acol);
                v0 = p[0];
                v1 = p[1];
            }
            uint4* d = (uint4*)(As + arow * A_LD + acol);
            d[0] = v0;
            d[1] = v1;
        }
        {
            const uint4* p = (const uint4*)(g_W2 + (long long)(k0 + brow) * 128 + bcol);
            uint4* d = (uint4*)(Bs + brow * B_LD + bcol);
            d[0] = p[0];
            d[1] = p[1];
        }
        __syncthreads();

#pragma unroll
        for (int ks = 0; ks < 32; ks += 16) {
            unsigned a[2][4];
#pragma unroll
            for (int mi = 0; mi < 2; mi++) {
                int m = wm * 32 + mi * 16 + (lane & 15);
                unsigned addr = as_base + (m * A_LD + ks + (lane >> 4) * 8) * 2;
                ldsm_x4(a[mi][0], a[mi][1], a[mi][2], a[mi][3], addr);
            }
            unsigned b[8][2];
#pragma unroll
            for (int nb = 0; nb < 4; nb++) {
                int n0 = wn * 64 + nb * 16;
                unsigned addr = bs_base + ((ks + (lane & 15)) * B_LD + n0 + (lane >> 4) * 8) * 2;
                unsigned r0, r1, r2, r3;
                ldsm_x4_t(r0, r1, r2, r3, addr);
                b[2 * nb][0] = r0;     b[2 * nb][1] = r1;
                b[2 * nb + 1][0] = r2; b[2 * nb + 1][1] = r3;
            }
#pragma unroll
            for (int mi = 0; mi < 2; mi++)
#pragma unroll
                for (int ni = 0; ni < 8; ni++)
                    mma16816(c[mi][ni], a[mi], b[ni]);
        }
        __syncthreads();
    }

    const float* bias = (wn == 0) ? bmu : bls;
    float* base = (wn == 0) ? out : (out + (long long)NN * OUTC);
#pragma unroll
    for (int mi = 0; mi < 2; mi++) {
        int row_a = row0 + wm * 32 + mi * 16 + (lane >> 2);
        int row_b = row_a + 8;
#pragma unroll
        for (int ni = 0; ni < 8; ni++) {
            int cc = ni * 8 + (lane & 3) * 2;
            float b0 = bias[cc], b1v = bias[cc + 1];
            if (row_a < NN) {
                float2 v = make_float2(c[mi][ni][0] + b0, c[mi][ni][1] + b1v);
                *(float2*)(base + (long long)row_a * OUTC + cc) = v;
            }
            if (row_b < NN) {
                float2 v = make_float2(c[mi][ni][2] + b0, c[mi][ni][3] + b1v);
                *(float2*)(base + (long long)row_b * OUTC + cc) = v;
            }
        }
    }
}

// ---------------------------------------------------------------------------
extern "C" void kernel_launch(void* const* d_in, const int* in_sizes, int n_in,
                              void* d_out, int out_size) {
    const float* x   = (const float*)d_in[0];
    const void*  ei  = d_in[1];
    const float* W1  = (const float*)d_in[2];
    const float* b1  = (const float*)d_in[3];
    const float* Wmu = (const float*)d_in[4];
    const float* bmu = (const float*)d_in[5];
    const float* Wls = (const float*)d_in[6];
    const float* bls = (const float*)d_in[7];
    float* out = (float*)d_out;

    const int E = in_sizes[1] / 2;

    const int nThr     = 256;
    const int nodeBlk  = (NN + nThr - 1) / nThr;
    const int edgeBlk4 = (E + nThr * 4 - 1) / (nThr * 4);
    const int scanBlk  = (NN + 1023) / 1024;   // 98
    const int propBlk  = (int)(((long long)NN * 32 + nThr - 1) / nThr);
    const int propBlkLo = (int)(((long long)NSPLIT * 32 + nThr - 1) / nThr);
    const int propBlkHi = (int)(((long long)(NN - NSPLIT) * 32 + nThr - 1) / nThr);
    const int gemmBlk  = (NN + 127) / 128;           // 782
    const int gemmBlkLo = NSPLIT / 128;               // 391
    const int gemmBlkHi = (NN - NSPLIT + 127) / 128;  // 391
    const int cvtWBlk  = (INCH * HID / 4 + nThr - 1) / nThr;
    const int cvtW2Blk = (HID * 128 + nThr - 1) / nThr;

    // One-time side-stream/event setup (host-side only; created on the first,
    // uncaptured correctness call; identical GPU work every call).
    static cudaStream_t sB = 0;
    static cudaEvent_t evFork = 0, evDinv = 0, evJoin = 0, evLo = 0, evG = 0;
    if (sB == 0) {
        cudaStreamCreateWithFlags(&sB, cudaStreamNonBlocking);
        cudaEventCreateWithFlags(&evFork, cudaEventDisableTiming);
        cudaEventCreateWithFlags(&evDinv, cudaEventDisableTiming);
        cudaEventCreateWithFlags(&evJoin, cudaEventDisableTiming);
        cudaEventCreateWithFlags(&evLo, cudaEventDisableTiming);
        cudaEventCreateWithFlags(&evG, cudaEventDisableTiming);
    }

    // ---- fork: side stream does weight conversions immediately ----
    cudaEventRecord(evFork, 0);
    cudaStreamWaitEvent(sB, evFork, 0);
    k_cvtW<<<cvtWBlk, nThr, 0, sB>>>(W1);
    k_cvtW2<<<cvtW2Blk, nThr, 0, sB>>>(Wmu, Wls);

    // ---- main stream: CSR build ----
    k_detect_zero<<<nodeBlk + 1, nThr>>>((const int*)ei);
    k_deg<<<edgeBlk4, nThr>>>(ei, E);
    k_scan_block<<<scanBlk, 1024>>>(NN);     // includes last-block top-scan
    k_finalize<<<nodeBlk, nThr>>>(NN, E);
    cudaEventRecord(evDinv, 0);              // dinv ready for gemm1h epilogue

    // side stream: gemm1h overlaps with scatter on the main stream
    cudaStreamWaitEvent(sB, evDinv, 0);
    k_gemm1h<<<gemmBlk, nThr, 0, sB>>>(x);
    cudaEventRecord(evJoin, sB);

    k_scatter<<<edgeBlk4, nThr>>>(ei, E);

    // ---- join: prop chain needs CSR (main) + g_H16a (side) ----
    cudaStreamWaitEvent(0, evJoin, 0);
    k_prop1<<<propBlk, nThr>>>(b1);

    // ---- pipelined prop2 / gemm2h: lo-half gemm overlaps hi-half prop ----
    k_prop2<<<propBlkLo, nThr>>>(0, NSPLIT);
    cudaEventRecord(evLo, 0);
    cudaStreamWaitEvent(sB, evLo, 0);
    k_gemm2h<<<gemmBlkLo, nThr, 0, sB>>>(bmu, bls, out, 0);
    cudaEventRecord(evG, sB);

    k_prop2<<<propBlkHi, nThr>>>(NSPLIT, NN);
    cudaStreamWaitEvent(0, evG, 0);
    k_gemm2h<<<gemmBlkHi, nThr>>>(bmu, bls, out, NSPLIT);
}

// round 16
// speedup vs baseline: 1.0573x; 1.0573x over previous
#include <cuda_runtime.h>
#include <cuda_fp16.h>

#define NN    100000
#define EEMAX 4000000
#define INCH  256
#define HID   128
#define OUTC  64
#define FULLMASK 0xffffffffu

// -------- scratch (device globals; referenced ONLY from device code) --------
__device__ __half g_W16[(size_t)INCH * HID];  // fp16 W1
__device__ __half g_W2[(size_t)HID * 128];    // fp16 [Wmu | Wls] packed
__device__ __half g_H16a[(size_t)NN * HID];   // gemm1 out (prescaled, fp16)
__device__ __half g_H16b[(size_t)NN * HID];   // prop1 out (prescaled, fp16)
__device__ __half g_H16c[(size_t)NN * HID];   // prop2 out (fp16, feeds gemm2)
__device__ float  g_dinv[NN];
__device__ int    g_deg[NN];
__device__ int    g_rowptr[NN + 1];
__device__ int    g_cursor[NN];
__device__ int    g_csr[EEMAX];
__device__ int    g_partial[128];
__device__ unsigned g_scanCtr = 0;
__device__ int    g_idx64;

// ---------------------------------------------------------------------------
// helpers
// ---------------------------------------------------------------------------
__device__ __forceinline__ float4 h4_to_f4(uint2 u) {
    __half2 h0 = *reinterpret_cast<__half2*>(&u.x);
    __half2 h1 = *reinterpret_cast<__half2*>(&u.y);
    float2 f0 = __half22float2(h0);
    float2 f1 = __half22float2(h1);
    return make_float4(f0.x, f0.y, f1.x, f1.y);
}

__device__ __forceinline__ uint2 f4_to_h4(float4 v) {
    __half2 h0 = __floats2half2_rn(v.x, v.y);
    __half2 h1 = __floats2half2_rn(v.z, v.w);
    uint2 u;
    u.x = *reinterpret_cast<unsigned*>(&h0);
    u.y = *reinterpret_cast<unsigned*>(&h1);
    return u;
}

__device__ __forceinline__ void ldsm_x4(unsigned& r0, unsigned& r1,
                                        unsigned& r2, unsigned& r3,
                                        unsigned addr) {
    asm volatile("ldmatrix.sync.aligned.m8n8.x4.shared.b16 {%0,%1,%2,%3}, [%4];"
                 : "=r"(r0), "=r"(r1), "=r"(r2), "=r"(r3) : "r"(addr));
}

__device__ __forceinline__ void ldsm_x4_t(unsigned& r0, unsigned& r1,
                                          unsigned& r2, unsigned& r3,
                                          unsigned addr) {
    asm volatile("ldmatrix.sync.aligned.m8n8.x4.trans.shared.b16 {%0,%1,%2,%3}, [%4];"
                 : "=r"(r0), "=r"(r1), "=r"(r2), "=r"(r3) : "r"(addr));
}

__device__ __forceinline__ void mma16816(float* c, const unsigned* a, const unsigned* b) {
    asm volatile(
        "mma.sync.aligned.m16n8k16.row.col.f32.f16.f16.f32 "
        "{%0,%1,%2,%3}, {%4,%5,%6,%7}, {%8,%9}, {%0,%1,%2,%3};"
        : "+f"(c[0]), "+f"(c[1]), "+f"(c[2]), "+f"(c[3])
        : "r"(a[0]), "r"(a[1]), "r"(a[2]), "r"(a[3]), "r"(b[0]), "r"(b[1]));
}

// ---------------------------------------------------------------------------
// weight conversion kernels
// ---------------------------------------------------------------------------
__global__ void k_cvtW(const float* __restrict__ w) {
    int i = blockIdx.x * blockDim.x + threadIdx.x;
    if (i < INCH * HID / 4)
        ((uint2*)g_W16)[i] = f4_to_h4(((const float4*)w)[i]);
}

__global__ void k_cvtW2(const float* __restrict__ wmu, const float* __restrict__ wls) {
    int i = blockIdx.x * blockDim.x + threadIdx.x;
    if (i < HID * 128) {
        int k = i >> 7, c = i & 127;
        float v = (c < 64) ? wmu[k * OUTC + c] : wls[k * OUTC + (c - 64)];
        g_W2[i] = __float2half_rn(v);
    }
}

// ---------------------------------------------------------------------------
// merged: block 0 = dtype detection; blocks 1.. = zero g_deg
// ---------------------------------------------------------------------------
__global__ void k_detect_zero(const int* __restrict__ ei32) {
    if (blockIdx.x == 0) {
        __shared__ int nz;
        if (threadIdx.x == 0) nz = 0;
        __syncthreads();
        int local = 0;
        for (int i = threadIdx.x; i < 4096; i += blockDim.x)
            if (ei32[2 * i + 1] != 0) local = 1;
        if (local) atomicOr(&nz, 1);
        __syncthreads();
        if (threadIdx.x == 0) g_idx64 = (nz == 0) ? 1 : 0;
    } else {
        int i = (blockIdx.x - 1) * blockDim.x + threadIdx.x;
        if (i < NN) g_deg[i] = 0;
    }
}

__device__ __forceinline__ int load_idx(const void* ei, long long pos) {
    if (g_idx64) return (int)((const long long*)ei)[pos];
    return ((const int*)ei)[pos];
}

// ---------------------------------------------------------------------------
// CSR construction (deg/scatter 4-edge unrolled)
// ---------------------------------------------------------------------------
__global__ void k_deg(const void* __restrict__ ei, int e) {
    int i = (blockIdx.x * blockDim.x + threadIdx.x) * 4;
    if (i + 4 <= e) {
        int d0 = load_idx(ei, (long long)e + i);
        int d1 = load_idx(ei, (long long)e + i + 1);
        int d2 = load_idx(ei, (long long)e + i + 2);
        int d3 = load_idx(ei, (long long)e + i + 3);
        atomicAdd(&g_deg[d0], 1);
        atomicAdd(&g_deg[d1], 1);
        atomicAdd(&g_deg[d2], 1);
        atomicAdd(&g_deg[d3], 1);
    } else {
        for (int j = i; j < e; j++)
            atomicAdd(&g_deg[load_idx(ei, (long long)e + j)], 1);
    }
}

// scan with last-block top-scan fold (removes the k_scan_top launch)
__global__ __launch_bounds__(1024) void k_scan_block(int n) {
    __shared__ int s[1024];
    __shared__ bool isLast;
    int t = threadIdx.x;
    int i = blockIdx.x * 1024 + t;
    int v = (i < n) ? g_deg[i] : 0;
    s[t] = v;
    __syncthreads();
#pragma unroll
    for (int off = 1; off < 1024; off <<= 1) {
        int x = (t >= off) ? s[t - off] : 0;
        __syncthreads();
        s[t] += x;
        __syncthreads();
    }
    if (i < n) g_rowptr[i] = s[t] - v;
    if (t == 1023) g_partial[blockIdx.x] = s[1023];

    // last block to finish performs the exclusive top-scan of g_partial
    __threadfence();
    if (t == 0) {
        unsigned prev = atomicAdd(&g_scanCtr, 1u);
        isLast = (prev == gridDim.x - 1);
    }
    __syncthreads();
    if (isLast && t == 0) {
        int run = 0;
        for (int b = 0; b < gridDim.x; b++) {
            int x = g_partial[b];
            g_partial[b] = run;
            run += x;
        }
        g_scanCtr = 0;   // reset for next graph replay (determinism)
        __threadfence();
    }
}

__global__ void k_finalize(int n, int e) {
    int i = blockIdx.x * blockDim.x + threadIdx.x;
    if (i < n) {
        int r = g_rowptr[i] + g_partial[i >> 10];
        g_rowptr[i] = r;
        g_cursor[i] = r;
        g_dinv[i]   = rsqrtf((float)g_deg[i] + 1.0f);
        if (i == 0) g_rowptr[n] = e;
    }
}

__global__ void k_scatter(const void* __restrict__ ei, int e) {
    int i = (blockIdx.x * blockDim.x + threadIdx.x) * 4;
    if (i + 4 <= e) {
        int s0 = load_idx(ei, i);
        int s1 = load_idx(ei, i + 1);
        int s2 = load_idx(ei, i + 2);
        int s3 = load_idx(ei, i + 3);
        int d0 = load_idx(ei, (long long)e + i);
        int d1 = load_idx(ei, (long long)e + i + 1);
        int d2 = load_idx(ei, (long long)e + i + 2);
        int d3 = load_idx(ei, (long long)e + i + 3);
        int p0 = atomicAdd(&g_cursor[d0], 1);
        int p1 = atomicAdd(&g_cursor[d1], 1);
        int p2 = atomicAdd(&g_cursor[d2], 1);
        int p3 = atomicAdd(&g_cursor[d3], 1);
        g_csr[p0] = s0;
        g_csr[p1] = s1;
        g_csr[p2] = s2;
        g_csr[p3] = s3;
    } else {
        for (int j = i; j < e; j++) {
            int s = load_idx(ei, j);
            int d = load_idx(ei, (long long)e + j);
            int pos = atomicAdd(&g_cursor[d], 1);
            g_csr[pos] = s;
        }
    }
}

// ---------------------------------------------------------------------------
// GEMM1 (tensor core): g_H16a = fp16( (X @ W1) * dinv[row] )
// ---------------------------------------------------------------------------
#define A_LD 40
#define B_LD 136

__global__ __launch_bounds__(256) void k_gemm1h(const float* __restrict__ X) {
    __shared__ __half As[128 * A_LD];
    __shared__ __half Bs[32 * B_LD];

    int t = threadIdx.x;
    int lane = t & 31;
    int w = t >> 5;
    int wm = w & 3;
    int wn = w >> 2;
    int row0 = blockIdx.x * 128;

    int arow = t >> 1, acol = (t & 1) * 16;
    int brow = t >> 3, bcol = (t & 7) * 16;
    int gr_a = row0 + arow;

    float c[2][8][4];
#pragma unroll
    for (int mi = 0; mi < 2; mi++)
#pragma unroll
        for (int ni = 0; ni < 8; ni++)
#pragma unroll
            for (int q = 0; q < 4; q++) c[mi][ni][q] = 0.f;

    unsigned as_base = (unsigned)__cvta_generic_to_shared(As);
    unsigned bs_base = (unsigned)__cvta_generic_to_shared(Bs);

    for (int k0 = 0; k0 < INCH; k0 += 32) {
        {
            float4 z = make_float4(0, 0, 0, 0);
            float4 f0 = z, f1 = z, f2 = z, f3 = z;
            if (gr_a < NN) {
                const float4* p = (const float4*)(X + (long long)gr_a * INCH + k0 + acol);
                f0 = p[0]; f1 = p[1]; f2 = p[2]; f3 = p[3];
            }
            uint2 h0 = f4_to_h4(f0), h1 = f4_to_h4(f1);
            uint2 h2 = f4_to_h4(f2), h3 = f4_to_h4(f3);
            uint4* d = (uint4*)(As + arow * A_LD + acol);
            d[0] = make_uint4(h0.x, h0.y, h1.x, h1.y);
            d[1] = make_uint4(h2.x, h2.y, h3.x, h3.y);
        }
        {
            const uint4* p = (const uint4*)(g_W16 + (long long)(k0 + brow) * HID + bcol);
            uint4* d = (uint4*)(Bs + brow * B_LD + bcol);
            d[0] = p[0];
            d[1] = p[1];
        }
        __syncthreads();

#pragma unroll
        for (int ks = 0; ks < 32; ks += 16) {
            unsigned a[2][4];
#pragma unroll
            for (int mi = 0; mi < 2; mi++) {
                int m = wm * 32 + mi * 16 + (lane & 15);
                unsigned addr = as_base + (m * A_LD + ks + (lane >> 4) * 8) * 2;
                ldsm_x4(a[mi][0], a[mi][1], a[mi][2], a[mi][3], addr);
            }
            unsigned b[8][2];
#pragma unroll
            for (int nb = 0; nb < 4; nb++) {
                int n0 = wn * 64 + nb * 16;
                unsigned addr = bs_base + ((ks + (lane & 15)) * B_LD + n0 + (lane >> 4) * 8) * 2;
                unsigned r0, r1, r2, r3;
                ldsm_x4_t(r0, r1, r2, r3, addr);
                b[2 * nb][0] = r0;     b[2 * nb][1] = r1;
                b[2 * nb + 1][0] = r2; b[2 * nb + 1][1] = r3;
            }
#pragma unroll
            for (int mi = 0; mi < 2; mi++)
#pragma unroll
                for (int ni = 0; ni < 8; ni++)
                    mma16816(c[mi][ni], a[mi], b[ni]);
        }
        __syncthreads();
    }

#pragma unroll
    for (int mi = 0; mi < 2; mi++) {
        int row_a = row0 + wm * 32 + mi * 16 + (lane >> 2);
        int row_b = row_a + 8;
        float sa = (row_a < NN) ? g_dinv[row_a] : 0.f;
        float sb = (row_b < NN) ? g_dinv[row_b] : 0.f;
#pragma unroll
        for (int ni = 0; ni < 8; ni++) {
            int col = wn * 64 + ni * 8 + (lane & 3) * 2;
            if (row_a < NN) {
                __half2 h = __floats2half2_rn(c[mi][ni][0] * sa, c[mi][ni][1] * sa);
                *(__half2*)(g_H16a + (long long)row_a * HID + col) = h;
            }
            if (row_b < NN) {
                __half2 h = __floats2half2_rn(c[mi][ni][2] * sb, c[mi][ni][3] * sb);
                *(__half2*)(g_H16a + (long long)row_b * HID + col) = h;
            }
        }
    }
}

// ---------------------------------------------------------------------------
// CSR propagation (fp16 gather, fp32 accumulate): warp per node.
// mode=1: fp16 out = h( dinv*relu(dn*sum + b1) )
// mode=2: fp16 out = h( dn*sum )
// ---------------------------------------------------------------------------
__device__ __forceinline__ void prop_body_h(const __half* __restrict__ in,
                                            __half* __restrict__ outh,
                                            const float* __restrict__ bias,
                                            int mode) {
    int node = (int)((blockIdx.x * (long long)blockDim.x + threadIdx.x) >> 5);
    int lane = threadIdx.x & 31;
    if (node >= NN) return;

    const uint2* IN = (const uint2*)in;
    int beg = g_rowptr[node];
    int end = g_rowptr[node + 1];

    float4 acc = h4_to_f4(IN[(long long)node * 32 + lane]);  // self-loop (pre-scaled)

    int e = beg;
    for (; e + 8 <= end; e += 8) {
        int s0 = g_csr[e];
        int s1 = g_csr[e + 1];
        int s2 = g_csr[e + 2];
        int s3 = g_csr[e + 3];
        int s4 = g_csr[e + 4];
        int s5 = g_csr[e + 5];
        int s6 = g_csr[e + 6];
        int s7 = g_csr[e + 7];
        uint2 u0 = IN[(long long)s0 * 32 + lane];
        uint2 u1 = IN[(long long)s1 * 32 + lane];
        uint2 u2 = IN[(long long)s2 * 32 + lane];
        uint2 u3 = IN[(long long)s3 * 32 + lane];
        uint2 u4 = IN[(long long)s4 * 32 + lane];
        uint2 u5 = IN[(long long)s5 * 32 + lane];
        uint2 u6 = IN[(long long)s6 * 32 + lane];
        uint2 u7 = IN[(long long)s7 * 32 + lane];
        float4 v0 = h4_to_f4(u0), v1 = h4_to_f4(u1), v2 = h4_to_f4(u2), v3 = h4_to_f4(u3);
        float4 v4 = h4_to_f4(u4), v5 = h4_to_f4(u5), v6 = h4_to_f4(u6), v7 = h4_to_f4(u7);
        acc.x += ((v0.x + v1.x) + (v2.x + v3.x)) + ((v4.x + v5.x) + (v6.x + v7.x));
        acc.y += ((v0.y + v1.y) + (v2.y + v3.y)) + ((v4.y + v5.y) + (v6.y + v7.y));
        acc.z += ((v0.z + v1.z) + (v2.z + v3.z)) + ((v4.z + v5.z) + (v6.z + v7.z));
        acc.w += ((v0.w + v1.w) + (v2.w + v3.w)) + ((v4.w + v5.w) + (v6.w + v7.w));
    }
    for (; e + 4 <= end; e += 4) {
        int s0 = g_csr[e];
        int s1 = g_csr[e + 1];
        int s2 = g_csr[e + 2];
        int s3 = g_csr[e + 3];
        float4 v0 = h4_to_f4(IN[(long long)s0 * 32 + lane]);
        float4 v1 = h4_to_f4(IN[(long long)s1 * 32 + lane]);
        float4 v2 = h4_to_f4(IN[(long long)s2 * 32 + lane]);
        float4 v3 = h4_to_f4(IN[(long long)s3 * 32 + lane]);
        acc.x += (v0.x + v1.x) + (v2.x + v3.x);
        acc.y += (v0.y + v1.y) + (v2.y + v3.y);
        acc.z += (v0.z + v1.z) + (v2.z + v3.z);
        acc.w += (v0.w + v1.w) + (v2.w + v3.w);
    }
    for (; e < end; e++) {
        int s = g_csr[e];
        float4 v = h4_to_f4(IN[(long long)s * 32 + lane]);
        acc.x += v.x; acc.y += v.y; acc.z += v.z; acc.w += v.w;
    }

    float dn = g_dinv[node];
    acc.x *= dn; acc.y *= dn; acc.z *= dn; acc.w *= dn;
    if (mode == 1) {
        float4 b = ((const float4*)bias)[lane];
        acc.x = fmaxf(acc.x + b.x, 0.f) * dn;
        acc.y = fmaxf(acc.y + b.y, 0.f) * dn;
        acc.z = fmaxf(acc.z + b.z, 0.f) * dn;
        acc.w = fmaxf(acc.w + b.w, 0.f) * dn;
    }
    ((uint2*)outh)[(long long)node * 32 + lane] = f4_to_h4(acc);
}

__global__ __launch_bounds__(256) void k_prop1(const float* __restrict__ b1) {
    prop_body_h(g_H16a, g_H16b, b1, 1);
}

__global__ __launch_bounds__(256) void k_prop2() {
    prop_body_h(g_H16b, g_H16c, (const float*)0, 2);
}

// ---------------------------------------------------------------------------
// GEMM2 (tensor core): [mu | ls] = g_H16c @ g_W2 + bias  (fp32 out)
// ---------------------------------------------------------------------------
__global__ __launch_bounds__(256) void k_gemm2h(const float* __restrict__ bmu,
                                                const float* __restrict__ bls,
                                                float* __restrict__ out) {
    __shared__ __half As[128 * A_LD];
    __shared__ __half Bs[32 * B_LD];

    int t = threadIdx.x;
    int lane = t & 31;
    int w = t >> 5;
    int wm = w & 3;
    int wn = w >> 2;
    int row0 = blockIdx.x * 128;

    int arow = t >> 1, acol = (t & 1) * 16;
    int brow = t >> 3, bcol = (t & 7) * 16;
    int gr_a = row0 + arow;

    float c[2][8][4];
#pragma unroll
    for (int mi = 0; mi < 2; mi++)
#pragma unroll
        for (int ni = 0; ni < 8; ni++)
#pragma unroll
            for (int q = 0; q < 4; q++) c[mi][ni][q] = 0.f;

    unsigned as_base = (unsigned)__cvta_generic_to_shared(As);
    unsigned bs_base = (unsigned)__cvta_generic_to_shared(Bs);

    for (int k0 = 0; k0 < HID; k0 += 32) {
        {
            uint4 z = make_uint4(0, 0, 0, 0);
            uint4 v0 = z, v1 = z;
            if (gr_a < NN) {
                const uint4* p = (const uint4*)(g_H16c + (long long)gr_a * HID + k0 + acol);
                v0 = p[0];
                v1 = p[1];
            }
            uint4* d = (uint4*)(As + arow * A_LD + acol);
            d[0] = v0;
            d[1] = v1;
        }
        {
            const uint4* p = (const uint4*)(g_W2 + (long long)(k0 + brow) * 128 + bcol);
            uint4* d = (uint4*)(Bs + brow * B_LD + bcol);
            d[0] = p[0];
            d[1] = p[1];
        }
        __syncthreads();

#pragma unroll
        for (int ks = 0; ks < 32; ks += 16) {
            unsigned a[2][4];
#pragma unroll
            for (int mi = 0; mi < 2; mi++) {
                int m = wm * 32 + mi * 16 + (lane & 15);
                unsigned addr = as_base + (m * A_LD + ks + (lane >> 4) * 8) * 2;
                ldsm_x4(a[mi][0], a[mi][1], a[mi][2], a[mi][3], addr);
            }
            unsigned b[8][2];
#pragma unroll
            for (int nb = 0; nb < 4; nb++) {
                int n0 = wn * 64 + nb * 16;
                unsigned addr = bs_base + ((ks + (lane & 15)) * B_LD + n0 + (lane >> 4) * 8) * 2;
                unsigned r0, r1, r2, r3;
                ldsm_x4_t(r0, r1, r2, r3, addr);
                b[2 * nb][0] = r0;     b[2 * nb][1] = r1;
                b[2 * nb + 1][0] = r2; b[2 * nb + 1][1] = r3;
            }
#pragma unroll
            for (int mi = 0; mi < 2; mi++)
#pragma unroll
                for (int ni = 0; ni < 8; ni++)
                    mma16816(c[mi][ni], a[mi], b[ni]);
        }
        __syncthreads();
    }

    const float* bias = (wn == 0) ? bmu : bls;
    float* base = (wn == 0) ? out : (out + (long long)NN * OUTC);
#pragma unroll
    for (int mi = 0; mi < 2; mi++) {
        int row_a = row0 + wm * 32 + mi * 16 + (lane >> 2);
        int row_b = row_a + 8;
#pragma unroll
        for (int ni = 0; ni < 8; ni++) {
            int cc = ni * 8 + (lane & 3) * 2;
            float b0 = bias[cc], b1v = bias[cc + 1];
            if (row_a < NN) {
                float2 v = make_float2(c[mi][ni][0] + b0, c[mi][ni][1] + b1v);
                *(float2*)(base + (long long)row_a * OUTC + cc) = v;
            }
            if (row_b < NN) {
                float2 v = make_float2(c[mi][ni][2] + b0, c[mi][ni][3] + b1v);
                *(float2*)(base + (long long)row_b * OUTC + cc) = v;
            }
        }
    }
}

// ---------------------------------------------------------------------------
extern "C" void kernel_launch(void* const* d_in, const int* in_sizes, int n_in,
                              void* d_out, int out_size) {
    const float* x   = (const float*)d_in[0];
    const void*  ei  = d_in[1];
    const float* W1  = (const float*)d_in[2];
    const float* b1  = (const float*)d_in[3];
    const float* Wmu = (const float*)d_in[4];
    const float* bmu = (const float*)d_in[5];
    const float* Wls = (const float*)d_in[6];
    const float* bls = (const float*)d_in[7];
    float* out = (float*)d_out;

    const int E = in_sizes[1] / 2;

    const int nThr     = 256;
    const int nodeBlk  = (NN + nThr - 1) / nThr;
    const int edgeBlk4 = (E + nThr * 4 - 1) / (nThr * 4);
    const int scanBlk  = (NN + 1023) / 1024;   // 98
    const int propBlk  = (int)(((long long)NN * 32 + nThr - 1) / nThr);
    const int gemmBlk  = (NN + 127) / 128;
    const int cvtWBlk  = (INCH * HID / 4 + nThr - 1) / nThr;
    const int cvtW2Blk = (HID * 128 + nThr - 1) / nThr;

    // One-time side-stream/event setup (host-side only; created on the first,
    // uncaptured correctness call; identical GPU work every call).
    static cudaStream_t sB = 0;
    static cudaEvent_t evFork = 0, evDinv = 0, evJoin = 0;
    if (sB == 0) {
        cudaStreamCreateWithFlags(&sB, cudaStreamNonBlocking);
        cudaEventCreateWithFlags(&evFork, cudaEventDisableTiming);
        cudaEventCreateWithFlags(&evDinv, cudaEventDisableTiming);
        cudaEventCreateWithFlags(&evJoin, cudaEventDisableTiming);
    }

    // ---- fork: side stream does weight conversions immediately ----
    cudaEventRecord(evFork, 0);
    cudaStreamWaitEvent(sB, evFork, 0);
    k_cvtW<<<cvtWBlk, nThr, 0, sB>>>(W1);
    k_cvtW2<<<cvtW2Blk, nThr, 0, sB>>>(Wmu, Wls);

    // ---- main stream: CSR build (scan-top folded into scan_block) ----
    k_detect_zero<<<nodeBlk + 1, nThr>>>((const int*)ei);
    k_deg<<<edgeBlk4, nThr>>>(ei, E);
    k_scan_block<<<scanBlk, 1024>>>(NN);
    k_finalize<<<nodeBlk, nThr>>>(NN, E);
    cudaEventRecord(evDinv, 0);          // dinv ready for gemm1h epilogue

    // side stream: gemm1h overlaps with scatter on the main stream
    cudaStreamWaitEvent(sB, evDinv, 0);
    k_gemm1h<<<gemmBlk, nThr, 0, sB>>>(x);
    cudaEventRecord(evJoin, sB);

    k_scatter<<<edgeBlk4, nThr>>>(ei, E);

    // ---- join: prop chain needs CSR (main) + g_H16a (side) ----
    cudaStreamWaitEvent(0, evJoin, 0);
    k_prop1<<<propBlk, nThr>>>(b1);
    k_prop2<<<propBlk, nThr>>>();
    k_gemm2h<<<gemmBlk, nThr>>>(bmu, bls, out);
}

// round 17
// speedup vs baseline: 1.0596x; 1.0022x over previous
#include <cuda_runtime.h>
#include <cuda_fp16.h>

#define NN    100000
#define EEMAX 4000000
#define INCH  256
#define HID   128
#define OUTC  64
#define FULLMASK 0xffffffffu

// -------- scratch (device globals; referenced ONLY from device code) --------
__device__ __half g_W16[(size_t)INCH * HID];  // fp16 W1
__device__ __half g_W2[(size_t)HID * 128];    // fp16 [Wmu | Wls] packed
__device__ __half g_H16a[(size_t)NN * HID];   // gemm1 out (prescaled, fp16)
__device__ __half g_H16b[(size_t)NN * HID];   // prop1 out (prescaled, fp16)
__device__ __half g_H16c[(size_t)NN * HID];   // prop2 out (fp16, feeds gemm2)
__device__ float  g_dinv[NN];
__device__ int    g_deg[NN];
__device__ int    g_rowptr[NN + 1];
__device__ int    g_cursor[NN];
__device__ int    g_csr[EEMAX];
__device__ int    g_partial[128];
__device__ unsigned g_scanCtr = 0;
__device__ int    g_idx64;

// ---------------------------------------------------------------------------
// helpers
// ---------------------------------------------------------------------------
__device__ __forceinline__ float4 h4_to_f4(uint2 u) {
    __half2 h0 = *reinterpret_cast<__half2*>(&u.x);
    __half2 h1 = *reinterpret_cast<__half2*>(&u.y);
    float2 f0 = __half22float2(h0);
    float2 f1 = __half22float2(h1);
    return make_float4(f0.x, f0.y, f1.x, f1.y);
}

__device__ __forceinline__ uint2 f4_to_h4(float4 v) {
    __half2 h0 = __floats2half2_rn(v.x, v.y);
    __half2 h1 = __floats2half2_rn(v.z, v.w);
    uint2 u;
    u.x = *reinterpret_cast<unsigned*>(&h0);
    u.y = *reinterpret_cast<unsigned*>(&h1);
    return u;
}

__device__ __forceinline__ void ldsm_x4(unsigned& r0, unsigned& r1,
                                        unsigned& r2, unsigned& r3,
                                        unsigned addr) {
    asm volatile("ldmatrix.sync.aligned.m8n8.x4.shared.b16 {%0,%1,%2,%3}, [%4];"
                 : "=r"(r0), "=r"(r1), "=r"(r2), "=r"(r3) : "r"(addr));
}

__device__ __forceinline__ void ldsm_x4_t(unsigned& r0, unsigned& r1,
                                          unsigned& r2, unsigned& r3,
                                          unsigned addr) {
    asm volatile("ldmatrix.sync.aligned.m8n8.x4.trans.shared.b16 {%0,%1,%2,%3}, [%4];"
                 : "=r"(r0), "=r"(r1), "=r"(r2), "=r"(r3) : "r"(addr));
}

__device__ __forceinline__ void mma16816(float* c, const unsigned* a, const unsigned* b) {
    asm volatile(
        "mma.sync.aligned.m16n8k16.row.col.f32.f16.f16.f32 "
        "{%0,%1,%2,%3}, {%4,%5,%6,%7}, {%8,%9}, {%0,%1,%2,%3};"
        : "+f"(c[0]), "+f"(c[1]), "+f"(c[2]), "+f"(c[3])
        : "r"(a[0]), "r"(a[1]), "r"(a[2]), "r"(a[3]), "r"(b[0]), "r"(b[1]));
}

// ---------------------------------------------------------------------------
// weight conversion kernels
// ---------------------------------------------------------------------------
__global__ void k_cvtW(const float* __restrict__ w) {
    int i = blockIdx.x * blockDim.x + threadIdx.x;
    if (i < INCH * HID / 4)
        ((uint2*)g_W16)[i] = f4_to_h4(((const float4*)w)[i]);
}

__global__ void k_cvtW2(const float* __restrict__ wmu, const float* __restrict__ wls) {
    int i = blockIdx.x * blockDim.x + threadIdx.x;
    if (i < HID * 128) {
        int k = i >> 7, c = i & 127;
        float v = (c < 64) ? wmu[k * OUTC + c] : wls[k * OUTC + (c - 64)];
        g_W2[i] = __float2half_rn(v);
    }
}

// ---------------------------------------------------------------------------
// merged: block 0 = dtype detection; blocks 1.. = zero g_deg
// ---------------------------------------------------------------------------
__global__ void k_detect_zero(const int* __restrict__ ei32) {
    if (blockIdx.x == 0) {
        __shared__ int nz;
        if (threadIdx.x == 0) nz = 0;
        __syncthreads();
        int local = 0;
        for (int i = threadIdx.x; i < 4096; i += blockDim.x)
            if (ei32[2 * i + 1] != 0) local = 1;
        if (local) atomicOr(&nz, 1);
        __syncthreads();
        if (threadIdx.x == 0) g_idx64 = (nz == 0) ? 1 : 0;
    } else {
        int i = (blockIdx.x - 1) * blockDim.x + threadIdx.x;
        if (i < NN) g_deg[i] = 0;
    }
}

__device__ __forceinline__ int load_idx(const void* ei, long long pos) {
    if (g_idx64) return (int)((const long long*)ei)[pos];
    return ((const int*)ei)[pos];
}

// load 4 consecutive indices starting at pos (pos % 4 == 0 guaranteed by caller)
__device__ __forceinline__ void load_idx4(const void* ei, long long pos,
                                          int& a, int& b, int& c, int& d) {
    if (g_idx64) {
        const longlong2* p = (const longlong2*)((const long long*)ei + pos);
        longlong2 u = p[0], v = p[1];
        a = (int)u.x; b = (int)u.y; c = (int)v.x; d = (int)v.y;
    } else {
        int4 u = *(const int4*)((const int*)ei + pos);
        a = u.x; b = u.y; c = u.z; d = u.w;
    }
}

// ---------------------------------------------------------------------------
// CSR construction (vectorized index loads; 4 edges/thread)
// ---------------------------------------------------------------------------
__global__ void k_deg(const void* __restrict__ ei, int e) {
    int i = (blockIdx.x * blockDim.x + threadIdx.x) * 4;
    if (i + 4 <= e && (e & 3) == 0) {
        int d0, d1, d2, d3;
        load_idx4(ei, (long long)e + i, d0, d1, d2, d3);
        atomicAdd(&g_deg[d0], 1);
        atomicAdd(&g_deg[d1], 1);
        atomicAdd(&g_deg[d2], 1);
        atomicAdd(&g_deg[d3], 1);
    } else {
        for (int j = i; j < e && j < i + 4; j++)
            atomicAdd(&g_deg[load_idx(ei, (long long)e + j)], 1);
    }
}

// scan with last-block top-scan fold; also computes dinv (deg in registers)
__global__ __launch_bounds__(1024) void k_scan_block(int n) {
    __shared__ int s[1024];
    __shared__ bool isLast;
    int t = threadIdx.x;
    int i = blockIdx.x * 1024 + t;
    int v = (i < n) ? g_deg[i] : 0;
    s[t] = v;
    if (i < n) g_dinv[i] = rsqrtf((float)v + 1.0f);
    __syncthreads();
#pragma unroll
    for (int off = 1; off < 1024; off <<= 1) {
        int x = (t >= off) ? s[t - off] : 0;
        __syncthreads();
        s[t] += x;
        __syncthreads();
    }
    if (i < n) g_rowptr[i] = s[t] - v;
    if (t == 1023) g_partial[blockIdx.x] = s[1023];

    // last block to finish performs the exclusive top-scan of g_partial
    __threadfence();
    if (t == 0) {
        unsigned prev = atomicAdd(&g_scanCtr, 1u);
        isLast = (prev == gridDim.x - 1);
    }
    __syncthreads();
    if (isLast && t == 0) {
        int run = 0;
        for (int b = 0; b < gridDim.x; b++) {
            int x = g_partial[b];
            g_partial[b] = run;
            run += x;
        }
        g_scanCtr = 0;   // reset for next graph replay (determinism)
        __threadfence();
    }
}

__global__ void k_finalize(int n, int e) {
    int i = blockIdx.x * blockDim.x + threadIdx.x;
    if (i < n) {
        int r = g_rowptr[i] + g_partial[i >> 10];
        g_rowptr[i] = r;
        g_cursor[i] = r;
        if (i == 0) g_rowptr[n] = e;
    }
}

__global__ void k_scatter(const void* __restrict__ ei, int e) {
    int i = (blockIdx.x * blockDim.x + threadIdx.x) * 4;
    if (i + 4 <= e && (e & 3) == 0) {
        int s0, s1, s2, s3, d0, d1, d2, d3;
        load_idx4(ei, i, s0, s1, s2, s3);
        load_idx4(ei, (long long)e + i, d0, d1, d2, d3);
        int p0 = atomicAdd(&g_cursor[d0], 1);
        int p1 = atomicAdd(&g_cursor[d1], 1);
        int p2 = atomicAdd(&g_cursor[d2], 1);
        int p3 = atomicAdd(&g_cursor[d3], 1);
        g_csr[p0] = s0;
        g_csr[p1] = s1;
        g_csr[p2] = s2;
        g_csr[p3] = s3;
    } else {
        for (int j = i; j < e && j < i + 4; j++) {
            int s = load_idx(ei, j);
            int d = load_idx(ei, (long long)e + j);
            int pos = atomicAdd(&g_cursor[d], 1);
            g_csr[pos] = s;
        }
    }
}

// ---------------------------------------------------------------------------
// GEMM1 (tensor core): g_H16a = fp16( (X @ W1) * dinv[row] )
// ---------------------------------------------------------------------------
#define A_LD 40
#define B_LD 136

__global__ __launch_bounds__(256) void k_gemm1h(const float* __restrict__ X) {
    __shared__ __half As[128 * A_LD];
    __shared__ __half Bs[32 * B_LD];

    int t = threadIdx.x;
    int lane = t & 31;
    int w = t >> 5;
    int wm = w & 3;
    int wn = w >> 2;
    int row0 = blockIdx.x * 128;

    int arow = t >> 1, acol = (t & 1) * 16;
    int brow = t >> 3, bcol = (t & 7) * 16;
    int gr_a = row0 + arow;

    float c[2][8][4];
#pragma unroll
    for (int mi = 0; mi < 2; mi++)
#pragma unroll
        for (int ni = 0; ni < 8; ni++)
#pragma unroll
            for (int q = 0; q < 4; q++) c[mi][ni][q] = 0.f;

    unsigned as_base = (unsigned)__cvta_generic_to_shared(As);
    unsigned bs_base = (unsigned)__cvta_generic_to_shared(Bs);

    for (int k0 = 0; k0 < INCH; k0 += 32) {
        {
            float4 z = make_float4(0, 0, 0, 0);
            float4 f0 = z, f1 = z, f2 = z, f3 = z;
            if (gr_a < NN) {
                const float4* p = (const float4*)(X + (long long)gr_a * INCH + k0 + acol);
                f0 = p[0]; f1 = p[1]; f2 = p[2]; f3 = p[3];
            }
            uint2 h0 = f4_to_h4(f0), h1 = f4_to_h4(f1);
            uint2 h2 = f4_to_h4(f2), h3 = f4_to_h4(f3);
            uint4* d = (uint4*)(As + arow * A_LD + acol);
            d[0] = make_uint4(h0.x, h0.y, h1.x, h1.y);
            d[1] = make_uint4(h2.x, h2.y, h3.x, h3.y);
        }
        {
            const uint4* p = (const uint4*)(g_W16 + (long long)(k0 + brow) * HID + bcol);
            uint4* d = (uint4*)(Bs + brow * B_LD + bcol);
            d[0] = p[0];
            d[1] = p[1];
        }
        __syncthreads();

#pragma unroll
        for (int ks = 0; ks < 32; ks += 16) {
            unsigned a[2][4];
#pragma unroll
            for (int mi = 0; mi < 2; mi++) {
                int m = wm * 32 + mi * 16 + (lane & 15);
                unsigned addr = as_base + (m * A_LD + ks + (lane >> 4) * 8) * 2;
                ldsm_x4(a[mi][0], a[mi][1], a[mi][2], a[mi][3], addr);
            }
            unsigned b[8][2];
#pragma unroll
            for (int nb = 0; nb < 4; nb++) {
                int n0 = wn * 64 + nb * 16;
                unsigned addr = bs_base + ((ks + (lane & 15)) * B_LD + n0 + (lane >> 4) * 8) * 2;
                unsigned r0, r1, r2, r3;
                ldsm_x4_t(r0, r1, r2, r3, addr);
                b[2 * nb][0] = r0;     b[2 * nb][1] = r1;
                b[2 * nb + 1][0] = r2; b[2 * nb + 1][1] = r3;
            }
#pragma unroll
            for (int mi = 0; mi < 2; mi++)
#pragma unroll
                for (int ni = 0; ni < 8; ni++)
                    mma16816(c[mi][ni], a[mi], b[ni]);
        }
        __syncthreads();
    }

#pragma unroll
    for (int mi = 0; mi < 2; mi++) {
        int row_a = row0 + wm * 32 + mi * 16 + (lane >> 2);
        int row_b = row_a + 8;
        float sa = (row_a < NN) ? g_dinv[row_a] : 0.f;
        float sb = (row_b < NN) ? g_dinv[row_b] : 0.f;
#pragma unroll
        for (int ni = 0; ni < 8; ni++) {
            int col = wn * 64 + ni * 8 + (lane & 3) * 2;
            if (row_a < NN) {
                __half2 h = __floats2half2_rn(c[mi][ni][0] * sa, c[mi][ni][1] * sa);
                *(__half2*)(g_H16a + (long long)row_a * HID + col) = h;
            }
            if (row_b < NN) {
                __half2 h = __floats2half2_rn(c[mi][ni][2] * sb, c[mi][ni][3] * sb);
                *(__half2*)(g_H16a + (long long)row_b * HID + col) = h;
            }
        }
    }
}

// ---------------------------------------------------------------------------
// CSR propagation (fp16 gather, fp32 accumulate): warp per node.
// mode=1: fp16 out = h( dinv*relu(dn*sum + b1) )
// mode=2: fp16 out = h( dn*sum )
// ---------------------------------------------------------------------------
__device__ __forceinline__ void prop_body_h(const __half* __restrict__ in,
                                            __half* __restrict__ outh,
                                            const float* __restrict__ bias,
                                            int mode) {
    int node = (int)((blockIdx.x * (long long)blockDim.x + threadIdx.x) >> 5);
    int lane = threadIdx.x & 31;
    if (node >= NN) return;

    const uint2* IN = (const uint2*)in;
    int beg = g_rowptr[node];
    int end = g_rowptr[node + 1];

    float4 acc = h4_to_f4(IN[(long long)node * 32 + lane]);  // self-loop (pre-scaled)

    int e = beg;
    for (; e + 8 <= end; e += 8) {
        int s0 = g_csr[e];
        int s1 = g_csr[e + 1];
        int s2 = g_csr[e + 2];
        int s3 = g_csr[e + 3];
        int s4 = g_csr[e + 4];
        int s5 = g_csr[e + 5];
        int s6 = g_csr[e + 6];
        int s7 = g_csr[e + 7];
        uint2 u0 = IN[(long long)s0 * 32 + lane];
        uint2 u1 = IN[(long long)s1 * 32 + lane];
        uint2 u2 = IN[(long long)s2 * 32 + lane];
        uint2 u3 = IN[(long long)s3 * 32 + lane];
        uint2 u4 = IN[(long long)s4 * 32 + lane];
        uint2 u5 = IN[(long long)s5 * 32 + lane];
        uint2 u6 = IN[(long long)s6 * 32 + lane];
        uint2 u7 = IN[(long long)s7 * 32 + lane];
        float4 v0 = h4_to_f4(u0), v1 = h4_to_f4(u1), v2 = h4_to_f4(u2), v3 = h4_to_f4(u3);
        float4 v4 = h4_to_f4(u4), v5 = h4_to_f4(u5), v6 = h4_to_f4(u6), v7 = h4_to_f4(u7);
        acc.x += ((v0.x + v1.x) + (v2.x + v3.x)) + ((v4.x + v5.x) + (v6.x + v7.x));
        acc.y += ((v0.y + v1.y) + (v2.y + v3.y)) + ((v4.y + v5.y) + (v6.y + v7.y));
        acc.z += ((v0.z + v1.z) + (v2.z + v3.z)) + ((v4.z + v5.z) + (v6.z + v7.z));
        acc.w += ((v0.w + v1.w) + (v2.w + v3.w)) + ((v4.w + v5.w) + (v6.w + v7.w));
    }
    for (; e + 4 <= end; e += 4) {
        int s0 = g_csr[e];
        int s1 = g_csr[e + 1];
        int s2 = g_csr[e + 2];
        int s3 = g_csr[e + 3];
        float4 v0 = h4_to_f4(IN[(long long)s0 * 32 + lane]);
        float4 v1 = h4_to_f4(IN[(long long)s1 * 32 + lane]);
        float4 v2 = h4_to_f4(IN[(long long)s2 * 32 + lane]);
        float4 v3 = h4_to_f4(IN[(long long)s3 * 32 + lane]);
        acc.x += (v0.x + v1.x) + (v2.x + v3.x);
        acc.y += (v0.y + v1.y) + (v2.y + v3.y);
        acc.z += (v0.z + v1.z) + (v2.z + v3.z);
        acc.w += (v0.w + v1.w) + (v2.w + v3.w);
    }
    for (; e < end; e++) {
        int s = g_csr[e];
        float4 v = h4_to_f4(IN[(long long)s * 32 + lane]);
        acc.x += v.x; acc.y += v.y; acc.z += v.z; acc.w += v.w;
    }

    float dn = g_dinv[node];
    acc.x *= dn; acc.y *= dn; acc.z *= dn; acc.w *= dn;
    if (mode == 1) {
        float4 b = ((const float4*)bias)[lane];
        acc.x = fmaxf(acc.x + b.x, 0.f) * dn;
        acc.y = fmaxf(acc.y + b.y, 0.f) * dn;
        acc.z = fmaxf(acc.z + b.z, 0.f) * dn;
        acc.w = fmaxf(acc.w + b.w, 0.f) * dn;
    }
    ((uint2*)outh)[(long long)node * 32 + lane] = f4_to_h4(acc);
}

__global__ __launch_bounds__(256) void k_prop1(const float* __restrict__ b1) {
    prop_body_h(g_H16a, g_H16b, b1, 1);
}

__global__ __launch_bounds__(256) void k_prop2() {
    prop_body_h(g_H16b, g_H16c, (const float*)0, 2);
}

// ---------------------------------------------------------------------------
// GEMM2 (tensor core): [mu | ls] = g_H16c @ g_W2 + bias  (fp32 out)
// ---------------------------------------------------------------------------
__global__ __launch_bounds__(256) void k_gemm2h(const float* __restrict__ bmu,
                                                const float* __restrict__ bls,
                                                float* __restrict__ out) {
    __shared__ __half As[128 * A_LD];
    __shared__ __half Bs[32 * B_LD];

    int t = threadIdx.x;
    int lane = t & 31;
    int w = t >> 5;
    int wm = w & 3;
    int wn = w >> 2;
    int row0 = blockIdx.x * 128;

    int arow = t >> 1, acol = (t & 1) * 16;
    int brow = t >> 3, bcol = (t & 7) * 16;
    int gr_a = row0 + arow;

    float c[2][8][4];
#pragma unroll
    for (int mi = 0; mi < 2; mi++)
#pragma unroll
        for (int ni = 0; ni < 8; ni++)
#pragma unroll
            for (int q = 0; q < 4; q++) c[mi][ni][q] = 0.f;

    unsigned as_base = (unsigned)__cvta_generic_to_shared(As);
    unsigned bs_base = (unsigned)__cvta_generic_to_shared(Bs);

    for (int k0 = 0; k0 < HID; k0 += 32) {
        {
            uint4 z = make_uint4(0, 0, 0, 0);
            uint4 v0 = z, v1 = z;
            if (gr_a < NN) {
                const uint4* p = (const uint4*)(g_H16c + (long long)gr_a * HID + k0 + acol);
                v0 = p[0];
                v1 = p[1];
            }
            uint4* d = (uint4*)(As + arow * A_LD + acol);
            d[0] = v0;
            d[1] = v1;
        }
        {
            const uint4* p = (const uint4*)(g_W2 + (long long)(k0 + brow) * 128 + bcol);
            uint4* d = (uint4*)(Bs + brow * B_LD + bcol);
            d[0] = p[0];
            d[1] = p[1];
        }
        __syncthreads();

#pragma unroll
        for (int ks = 0; ks < 32; ks += 16) {
            unsigned a[2][4];
#pragma unroll
            for (int mi = 0; mi < 2; mi++) {
                int m = wm * 32 + mi * 16 + (lane & 15);
                unsigned addr = as_base + (m * A_LD + ks + (lane >> 4) * 8) * 2;
                ldsm_x4(a[mi][0], a[mi][1], a[mi][2], a[mi][3], addr);
            }
            unsigned b[8][2];
#pragma unroll
            for (int nb = 0; nb < 4; nb++) {
                int n0 = wn * 64 + nb * 16;
                unsigned addr = bs_base + ((ks + (lane & 15)) * B_LD + n0 + (lane >> 4) * 8) * 2;
                unsigned r0, r1, r2, r3;
                ldsm_x4_t(r0, r1, r2, r3, addr);
                b[2 * nb][0] = r0;     b[2 * nb][1] = r1;
                b[2 * nb + 1][0] = r2; b[2 * nb + 1][1] = r3;
            }
#pragma unroll
            for (int mi = 0; mi < 2; mi++)
#pragma unroll
                for (int ni = 0; ni < 8; ni++)
                    mma16816(c[mi][ni], a[mi], b[ni]);
        }
        __syncthreads();
    }

    const float* bias = (wn == 0) ? bmu : bls;
    float* base = (wn == 0) ? out : (out + (long long)NN * OUTC);
#pragma unroll
    for (int mi = 0; mi < 2; mi++) {
        int row_a = row0 + wm * 32 + mi * 16 + (lane >> 2);
        int row_b = row_a + 8;
#pragma unroll
        for (int ni = 0; ni < 8; ni++) {
            int cc = ni * 8 + (lane & 3) * 2;
            float b0 = bias[cc], b1v = bias[cc + 1];
            if (row_a < NN) {
                float2 v = make_float2(c[mi][ni][0] + b0, c[mi][ni][1] + b1v);
                *(float2*)(base + (long long)row_a * OUTC + cc) = v;
            }
            if (row_b < NN) {
                float2 v = make_float2(c[mi][ni][2] + b0, c[mi][ni][3] + b1v);
                *(float2*)(base + (long long)row_b * OUTC + cc) = v;
            }
        }
    }
}

// ---------------------------------------------------------------------------
extern "C" void kernel_launch(void* const* d_in, const int* in_sizes, int n_in,
                              void* d_out, int out_size) {
    const float* x   = (const float*)d_in[0];
    const void*  ei  = d_in[1];
    const float* W1  = (const float*)d_in[2];
    const float* b1  = (const float*)d_in[3];
    const float* Wmu = (const float*)d_in[4];
    const float* bmu = (const float*)d_in[5];
    const float* Wls = (const float*)d_in[6];
    const float* bls = (const float*)d_in[7];
    float* out = (float*)d_out;

    const int E = in_sizes[1] / 2;

    const int nThr     = 256;
    const int nodeBlk  = (NN + nThr - 1) / nThr;
    const int edgeBlk4 = (E + nThr * 4 - 1) / (nThr * 4);
    const int scanBlk  = (NN + 1023) / 1024;   // 98
    const int propBlk  = (int)(((long long)NN * 32 + nThr - 1) / nThr);
    const int gemmBlk  = (NN + 127) / 128;
    const int cvtWBlk  = (INCH * HID / 4 + nThr - 1) / nThr;
    const int cvtW2Blk = (HID * 128 + nThr - 1) / nThr;

    // One-time side-stream/event setup (host-side only; created on the first,
    // uncaptured correctness call; identical GPU work every call).
    static cudaStream_t sB = 0;
    static cudaEvent_t evFork = 0, evDinv = 0, evJoin = 0;
    if (sB == 0) {
        cudaStreamCreateWithFlags(&sB, cudaStreamNonBlocking);
        cudaEventCreateWithFlags(&evFork, cudaEventDisableTiming);
        cudaEventCreateWithFlags(&evDinv, cudaEventDisableTiming);
        cudaEventCreateWithFlags(&evJoin, cudaEventDisableTiming);
    }

    // ---- fork: side stream does weight conversions immediately ----
    cudaEventRecord(evFork, 0);
    cudaStreamWaitEvent(sB, evFork, 0);
    k_cvtW<<<cvtWBlk, nThr, 0, sB>>>(W1);
    k_cvtW2<<<cvtW2Blk, nThr, 0, sB>>>(Wmu, Wls);

    // ---- main stream: CSR build ----
    k_detect_zero<<<nodeBlk + 1, nThr>>>((const int*)ei);
    k_deg<<<edgeBlk4, nThr>>>(ei, E);
    k_scan_block<<<scanBlk, 1024>>>(NN);     // also computes dinv
    k_finalize<<<nodeBlk, nThr>>>(NN, E);
    cudaEventRecord(evDinv, 0);              // dinv+rowptr ready

    // side stream: gemm1h overlaps with scatter on the main stream
    cudaStreamWaitEvent(sB, evDinv, 0);
    k_gemm1h<<<gemmBlk, nThr, 0, sB>>>(x);
    cudaEventRecord(evJoin, sB);

    k_scatter<<<edgeBlk4, nThr>>>(ei, E);

    // ---- join: prop chain needs CSR (main) + g_H16a (side) ----
    cudaStreamWaitEvent(0, evJoin, 0);
    k_prop1<<<propBlk, nThr>>>(b1);
    k_prop2<<<propBlk, nThr>>>();
    k_gemm2h<<<gemmBlk, nThr>>>(bmu, bls, out);
}